// round 2
// baseline (speedup 1.0000x reference)
#include <cuda_runtime.h>
#include <math.h>

// Problem constants (fixed by the dataset)
#define N_NODES 50000
#define N_EDGES 800000
#define ET_EDGES (N_NODES + N_EDGES)   // edges + self loops
#define HWID 256                        // heads*hid for layers 0/1
#define CDIM 64

// ---------------- scratch (device globals; no allocation allowed) -------------
static __device__ float g_h   [(size_t)N_NODES * HWID];
static __device__ float g_agg [(size_t)N_NODES * HWID];
static __device__ float g_as  [N_NODES * 4];
static __device__ float g_ad  [N_NODES * 4];
static __device__ float g_emax[N_NODES * 4];
static __device__ float g_den [N_NODES * 4];
static __device__ float g_ex  [(size_t)ET_EDGES * 4];
static __device__ float g_sum [HWID];
static __device__ float g_sq  [HWID];
static __device__ float g_scl [HWID];
static __device__ float g_sft [HWID];
static __device__ float g_cls [N_NODES * 32];

// ---------------- helpers -----------------------------------------------------
__device__ __forceinline__ void atomicMaxF(float* addr, float v) {
    if (v >= 0.f) atomicMax((int*)addr, __float_as_int(v));
    else          atomicMin((unsigned int*)addr, (unsigned int)__float_as_int(v));
}

__device__ __forceinline__ void redAdd4(float* p, float4 v) {
#if __CUDA_ARCH__ >= 900
    asm volatile("red.global.add.v4.f32 [%0], {%1,%2,%3,%4};"
                 :: "l"(p), "f"(v.x), "f"(v.y), "f"(v.z), "f"(v.w) : "memory");
#else
    atomicAdd(p + 0, v.x); atomicAdd(p + 1, v.y);
    atomicAdd(p + 2, v.z); atomicAdd(p + 3, v.w);
#endif
}

__global__ void fill_k(float* p, float v, int n) {
    int i = blockIdx.x * blockDim.x + threadIdx.x;
    if (i < n) p[i] = v;
}

__global__ void fill4_k(float4* p, float v, int n4) {
    int i = blockIdx.x * blockDim.x + threadIdx.x;
    if (i < n4) p[i] = make_float4(v, v, v, v);
}

__global__ void addbias_k(float* p, const float* __restrict__ b, int n, int C) {
    int i = blockIdx.x * blockDim.x + threadIdx.x;
    if (i < n) p[i] += b[i % C];
}

// ---------------- SGEMM: C[M,N] = A[M,K] @ B[K,N] (+bias, +relu) --------------
#define BM 128
#define BN 64
#define BK 16
#define TM 8
#define TN 4
__global__ __launch_bounds__(256) void sgemm_k(
    const float* __restrict__ A, const float* __restrict__ B,
    float* __restrict__ C, int M, int N, int K,
    const float* __restrict__ bias, int relu)
{
    __shared__ float As[BK][BM];
    __shared__ float Bs[BK][BN];
    int tid = threadIdx.x;
    int tx = tid % (BN / TN);   // 16
    int ty = tid / (BN / TN);   // 16
    int rowBase = blockIdx.y * BM;
    int colBase = blockIdx.x * BN;

    float acc[TM][TN];
#pragma unroll
    for (int i = 0; i < TM; i++)
#pragma unroll
        for (int j = 0; j < TN; j++) acc[i][j] = 0.f;

    for (int k0 = 0; k0 < K; k0 += BK) {
        for (int i = tid; i < BM * BK; i += 256) {
            int r = i / BK, c = i % BK;
            int gr = rowBase + r, gc = k0 + c;
            As[c][r] = (gr < M && gc < K) ? A[(size_t)gr * K + gc] : 0.f;
        }
        for (int i = tid; i < BK * BN; i += 256) {
            int r = i / BN, c = i % BN;
            int gr = k0 + r, gc = colBase + c;
            Bs[r][c] = (gr < K && gc < N) ? B[(size_t)gr * N + gc] : 0.f;
        }
        __syncthreads();
#pragma unroll
        for (int k = 0; k < BK; k++) {
            float a[TM], b[TN];
#pragma unroll
            for (int i = 0; i < TM; i++) a[i] = As[k][ty * TM + i];
#pragma unroll
            for (int j = 0; j < TN; j++) b[j] = Bs[k][tx * TN + j];
#pragma unroll
            for (int i = 0; i < TM; i++)
#pragma unroll
                for (int j = 0; j < TN; j++) acc[i][j] += a[i] * b[j];
        }
        __syncthreads();
    }
#pragma unroll
    for (int i = 0; i < TM; i++) {
        int gr = rowBase + ty * TM + i;
        if (gr >= M) continue;
#pragma unroll
        for (int j = 0; j < TN; j++) {
            int gc = colBase + tx * TN + j;
            if (gc >= N) continue;
            float v = acc[i][j];
            if (bias) v += bias[gc];
            if (relu) v = fmaxf(v, 0.f);
            C[(size_t)gr * N + gc] = v;
        }
    }
}

// ---------------- attention coefficients: a_s[n,h], a_d[n,h] ------------------
// one warp per (node, head); lanes stride over C=64 channels (coalesced)
__global__ void attn_coef_k(const float* __restrict__ h,
                            const float* __restrict__ asw,
                            const float* __restrict__ adw,
                            float* __restrict__ as_o, float* __restrict__ ad_o,
                            int n, int H)
{
    int w = (blockIdx.x * blockDim.x + threadIdx.x) >> 5;
    int lane = threadIdx.x & 31;
    if (w >= n * H) return;
    int node = w / H, hd = w - node * H;
    const float* row = h + (size_t)node * H * CDIM + hd * CDIM;
    float s = 0.f, d = 0.f;
#pragma unroll
    for (int c = lane; c < CDIM; c += 32) {
        float v = row[c];
        s += v * asw[hd * CDIM + c];
        d += v * adw[hd * CDIM + c];
    }
#pragma unroll
    for (int o = 16; o; o >>= 1) {
        s += __shfl_down_sync(0xFFFFFFFFu, s, o);
        d += __shfl_down_sync(0xFFFFFFFFu, d, o);
    }
    if (!lane) { as_o[w] = s; ad_o[w] = d; }
}

// ---------------- segment max over dst ----------------------------------------
__global__ void edge_max_k(const int* __restrict__ src, const int* __restrict__ dst,
                           const float* __restrict__ as_o, const float* __restrict__ ad_o,
                           float* emax, int E, int et, int H)
{
    int idx = blockIdx.x * blockDim.x + threadIdx.x;
    if (idx >= et * H) return;
    int e = idx / H, hd = idx - e * H;
    int s, d;
    if (e < E) { s = src[e]; d = dst[e]; } else { s = d = e - E; }
    float v = as_o[s * H + hd] + ad_o[d * H + hd];
    v = v > 0.f ? v : 0.2f * v;
    atomicMaxF(&emax[d * H + hd], v);
}

// ---------------- exp(e - max) + segment sum ----------------------------------
__global__ void edge_exp_k(const int* __restrict__ src, const int* __restrict__ dst,
                           const float* __restrict__ as_o, const float* __restrict__ ad_o,
                           const float* __restrict__ emax, float* den, float* ex,
                           int E, int et, int H)
{
    int idx = blockIdx.x * blockDim.x + threadIdx.x;
    if (idx >= et * H) return;
    int e = idx / H, hd = idx - e * H;
    int s, d;
    if (e < E) { s = src[e]; d = dst[e]; } else { s = d = e - E; }
    float v = as_o[s * H + hd] + ad_o[d * H + hd];
    v = v > 0.f ? v : 0.2f * v;
    float ev = expf(v - emax[d * H + hd]);
    ex[idx] = ev;
    atomicAdd(&den[d * H + hd], ev);
}

// ---------------- message scatter: out[dst] += alpha * h[src] -----------------
// one warp per edge; float4 gather + red.global.add.v4 scatter
template <int H>
__global__ void scatter_k(const int* __restrict__ src, const int* __restrict__ dst,
                          const float* __restrict__ h, const float* __restrict__ ex,
                          const float* __restrict__ den, float* __restrict__ out,
                          int E, int et)
{
    int w = (blockIdx.x * blockDim.x + threadIdx.x) >> 5;
    int lane = threadIdx.x & 31;
    if (w >= et) return;
    int s, d;
    if (w < E) { s = src[w]; d = dst[w]; } else { s = d = w - E; }
    float a = 0.f;
    if (lane < H) a = ex[(size_t)w * H + lane] / den[d * H + lane];
    const float4* hr4 = (const float4*)(h + (size_t)s * H * CDIM);
    float*        od  = out + (size_t)d * H * CDIM;
    const int NV = H * CDIM / 4;                    // float4s per row
#pragma unroll
    for (int k = 0; k < NV; k += 32) {
        int idx = k + lane;
        if (idx < NV) {
            int head = idx / (CDIM / 4);
            float al = __shfl_sync(0xFFFFFFFFu, a, head);
            float4 v = hr4[idx];
            v.x *= al; v.y *= al; v.z *= al; v.w *= al;
            redAdd4(od + idx * 4, v);
        }
    }
}

// ---------------- batch norm (C=256 channels) ---------------------------------
__global__ void bn_stats_k(const float* __restrict__ x, int n, float* sum, float* sq) {
    int ch = threadIdx.x;   // 256 threads
    float s = 0.f, s2 = 0.f;
    for (int r = blockIdx.x; r < n; r += gridDim.x) {
        float v = x[(size_t)r * HWID + ch];
        s += v; s2 += v * v;
    }
    atomicAdd(&sum[ch], s);
    atomicAdd(&sq[ch], s2);
}

__global__ void bn_fin_k(const float* sum, const float* sq,
                         const float* __restrict__ g, const float* __restrict__ be,
                         int n, float* scl, float* sft) {
    int ch = threadIdx.x;
    float mu = sum[ch] / (float)n;
    float var = fmaxf(sq[ch] / (float)n - mu * mu, 0.f);
    float r = rsqrtf(var + 1e-5f);
    float s = g[ch] * r;
    scl[ch] = s;
    sft[ch] = be[ch] - mu * s;
}

__global__ void bn_apply_elu_k(const float4* __restrict__ in, float4* __restrict__ outp,
                               const float* __restrict__ scl, const float* __restrict__ sft,
                               int n4) {
    int i = blockIdx.x * blockDim.x + threadIdx.x;
    if (i >= n4) return;
    int c4 = (i & (HWID / 4 - 1)) * 4;
    float4 v = in[i];
    v.x = v.x * scl[c4 + 0] + sft[c4 + 0];
    v.y = v.y * scl[c4 + 1] + sft[c4 + 1];
    v.z = v.z * scl[c4 + 2] + sft[c4 + 2];
    v.w = v.w * scl[c4 + 3] + sft[c4 + 3];
    v.x = v.x > 0.f ? v.x : expm1f(v.x);
    v.y = v.y > 0.f ? v.y : expm1f(v.y);
    v.z = v.z > 0.f ? v.z : expm1f(v.z);
    v.w = v.w > 0.f ? v.w : expm1f(v.w);
    outp[i] = v;
}

// ---------------- host-side orchestration -------------------------------------
static void run_sgemm(const float* A, const float* B, float* C, int M, int N, int K,
                      const float* bias, int relu) {
    dim3 grid((N + BN - 1) / BN, (M + BM - 1) / BM);
    sgemm_k<<<grid, 256>>>(A, B, C, M, N, K, bias, relu);
}

static void gat_aggregate(const int* src, const int* dst,
                          const float* h, const float* asw, const float* adw,
                          float* asb, float* adb, float* emaxb, float* denb, float* exb,
                          float* aggout, int n, int H)
{
    int nh = n * H;
    attn_coef_k<<<(nh * 32 + 255) / 256, 256>>>(h, asw, adw, asb, adb, n, H);
    fill_k<<<(nh + 255) / 256, 256>>>(emaxb, -3.4e38f, nh);
    fill_k<<<(nh + 255) / 256, 256>>>(denb, 0.f, nh);
    int tot4 = n * H * CDIM / 4;
    fill4_k<<<(tot4 + 255) / 256, 256>>>((float4*)aggout, 0.f, tot4);
    int etH = ET_EDGES * H;
    edge_max_k<<<(etH + 255) / 256, 256>>>(src, dst, asb, adb, emaxb, N_EDGES, ET_EDGES, H);
    edge_exp_k<<<(etH + 255) / 256, 256>>>(src, dst, asb, adb, emaxb, denb, exb, N_EDGES, ET_EDGES, H);
    long long thr = (long long)ET_EDGES * 32;
    int blocks = (int)((thr + 255) / 256);
    if (H == 4)
        scatter_k<4><<<blocks, 256>>>(src, dst, h, exb, denb, aggout, N_EDGES, ET_EDGES);
    else
        scatter_k<1><<<blocks, 256>>>(src, dst, h, exb, denb, aggout, N_EDGES, ET_EDGES);
}

static void bn_elu(const float* in, float* outp, const float* g, const float* be, int n,
                   float* sumb, float* sqb, float* sclb, float* sftb)
{
    fill_k<<<1, 256>>>(sumb, 0.f, HWID);
    fill_k<<<1, 256>>>(sqb, 0.f, HWID);
    bn_stats_k<<<512, 256>>>(in, n, sumb, sqb);
    bn_fin_k<<<1, 256>>>(sumb, sqb, g, be, n, sclb, sftb);
    bn_apply_elu_k<<<(n * HWID / 4 + 255) / 256, 256>>>(
        (const float4*)in, (float4*)outp, sclb, sftb, n * HWID / 4);
}

extern "C" void kernel_launch(void* const* d_in, const int* in_sizes, int n_in,
                              void* d_out, int out_size)
{
    const float* x   = (const float*)d_in[0];
    const int*   ei  = (const int*)  d_in[1];
    const float* W0  = (const float*)d_in[2];
    const float* as0 = (const float*)d_in[3];
    const float* ad0 = (const float*)d_in[4];
    // b0 (d_in[5]) cancels through BatchNorm — skipped
    const float* W1  = (const float*)d_in[6];
    const float* as1 = (const float*)d_in[7];
    const float* ad1 = (const float*)d_in[8];
    // b1 (d_in[9]) cancels through BatchNorm — skipped
    const float* W2  = (const float*)d_in[10];
    const float* as2 = (const float*)d_in[11];
    const float* ad2 = (const float*)d_in[12];
    const float* b2  = (const float*)d_in[13];
    const float* g0  = (const float*)d_in[14];
    const float* be0 = (const float*)d_in[15];
    const float* g1  = (const float*)d_in[16];
    const float* be1 = (const float*)d_in[17];
    const float* Wc1 = (const float*)d_in[18];
    const float* bc1 = (const float*)d_in[19];
    const float* Wc2 = (const float*)d_in[20];
    const float* bc2 = (const float*)d_in[21];
    float* out = (float*)d_out;

    const int n = N_NODES;
    const int* src = ei;
    const int* dst = ei + N_EDGES;

    float *hbuf, *aggbuf, *asb, *adb, *emaxb, *denb, *exb;
    float *sumb, *sqb, *sclb, *sftb, *clsb;
    cudaGetSymbolAddress((void**)&hbuf,  g_h);
    cudaGetSymbolAddress((void**)&aggbuf, g_agg);
    cudaGetSymbolAddress((void**)&asb,   g_as);
    cudaGetSymbolAddress((void**)&adb,   g_ad);
    cudaGetSymbolAddress((void**)&emaxb, g_emax);
    cudaGetSymbolAddress((void**)&denb,  g_den);
    cudaGetSymbolAddress((void**)&exb,   g_ex);
    cudaGetSymbolAddress((void**)&sumb,  g_sum);
    cudaGetSymbolAddress((void**)&sqb,   g_sq);
    cudaGetSymbolAddress((void**)&sclb,  g_scl);
    cudaGetSymbolAddress((void**)&sftb,  g_sft);
    cudaGetSymbolAddress((void**)&clsb,  g_cls);

    // ---- GAT layer 0: 128 -> 4x64 (concat) ----
    run_sgemm(x, W0, hbuf, n, 256, 128, nullptr, 0);
    gat_aggregate(src, dst, hbuf, as0, ad0, asb, adb, emaxb, denb, exb, aggbuf, n, 4);
    bn_elu(aggbuf, hbuf, g0, be0, n, sumb, sqb, sclb, sftb);

    // ---- GAT layer 1: 256 -> 4x64 (concat) ----
    run_sgemm(hbuf, W1, aggbuf, n, 256, 256, nullptr, 0);
    gat_aggregate(src, dst, aggbuf, as1, ad1, asb, adb, emaxb, denb, exb, hbuf, n, 4);
    bn_elu(hbuf, aggbuf, g1, be1, n, sumb, sqb, sclb, sftb);

    // ---- GAT layer 2: 256 -> 1x64 ----
    run_sgemm(aggbuf, W2, hbuf, n, 64, 256, nullptr, 0);
    gat_aggregate(src, dst, hbuf, as2, ad2, asb, adb, emaxb, denb, exb, aggbuf, n, 1);
    addbias_k<<<(n * 64 + 255) / 256, 256>>>(aggbuf, b2, n * 64, 64);

    // ---- classifier: 64 -> 32 (relu) -> 2 ----
    run_sgemm(aggbuf, Wc1, clsb, n, 32, 64, bc1, 1);
    run_sgemm(clsb, Wc2, out, n, 2, 32, bc2, 0);
}

// round 3
// speedup vs baseline: 1.3894x; 1.3894x over previous
#include <cuda_runtime.h>
#include <math.h>

// Problem constants (fixed by the dataset)
#define N_NODES 50000
#define N_EDGES 800000
#define ET_EDGES (N_NODES + N_EDGES)   // edges + self loops
#define HWID 256                        // heads*hid for layers 0/1
#define CDIM 64

// ---------------- scratch (device globals; no allocation allowed) -------------
static __device__ float g_h   [(size_t)N_NODES * HWID];
static __device__ float g_agg [(size_t)N_NODES * HWID];
static __device__ float g_as  [N_NODES * 4];
static __device__ float g_ad  [N_NODES * 4];
static __device__ float g_emax[N_NODES * 4];
static __device__ float g_den [N_NODES * 4];
static __device__ float g_ex  [(size_t)ET_EDGES * 4];
static __device__ float g_sum [HWID];
static __device__ float g_sq  [HWID];
static __device__ float g_scl [HWID];
static __device__ float g_sft [HWID];
static __device__ float g_cls [N_NODES * 32];

// ---------------- helpers -----------------------------------------------------
__device__ __forceinline__ void atomicMaxF(float* addr, float v) {
    if (v >= 0.f) atomicMax((int*)addr, __float_as_int(v));
    else          atomicMin((unsigned int*)addr, (unsigned int)__float_as_int(v));
}

__device__ __forceinline__ void redAdd4(float* p, float4 v) {
    asm volatile("red.global.add.v4.f32 [%0], {%1,%2,%3,%4};"
                 :: "l"(p), "f"(v.x), "f"(v.y), "f"(v.z), "f"(v.w) : "memory");
}

__device__ __forceinline__ unsigned int f2tf32(float f) {
    unsigned int u;
    asm("cvt.rna.tf32.f32 %0, %1;" : "=r"(u) : "f"(f));
    return u;
}

__global__ void fill_k(float* p, float v, int n) {
    int i = blockIdx.x * blockDim.x + threadIdx.x;
    if (i < n) p[i] = v;
}

__global__ void fill4_k(float4* p, float v, int n4) {
    int i = blockIdx.x * blockDim.x + threadIdx.x;
    if (i < n4) p[i] = make_float4(v, v, v, v);
}

__global__ void addbias_k(float* p, const float* __restrict__ b, int n, int C) {
    int i = blockIdx.x * blockDim.x + threadIdx.x;
    if (i < n) p[i] += b[i % C];
}

// ---------------- TF32 tensor-core GEMM: C[M,N] = A[M,K] @ B[K,N] -------------
// BM=128, BN=64, BK=32; 256 threads = 8 warps (4x2), warp tile 32x32.
// Requires: K % 32 == 0, N % 64 == 0. M arbitrary (predicated).
__global__ __launch_bounds__(256) void tf32gemm_k(
    const float* __restrict__ A, const float* __restrict__ B,
    float* __restrict__ C, int M, int N, int K)
{
    __shared__ float As[128][36];   // [m][k], stride 36 -> frag loads conflict-free
    __shared__ float Bs[32][72];    // [k][n], stride 72 -> frag loads conflict-free

    int tid = threadIdx.x;
    int warp = tid >> 5, lane = tid & 31;
    int wm = (warp & 3) * 32;       // warp row offset in tile
    int wn = (warp >> 2) * 32;      // warp col offset in tile
    int rowBase = blockIdx.y * 128;
    int colBase = blockIdx.x * 64;
    int mrow = lane >> 2;           // 0..7
    int kcol = lane & 3;            // 0..3

    float acc[2][4][4];
#pragma unroll
    for (int mi = 0; mi < 2; mi++)
#pragma unroll
        for (int ni = 0; ni < 4; ni++)
#pragma unroll
            for (int r = 0; r < 4; r++) acc[mi][ni][r] = 0.f;

    for (int k0 = 0; k0 < K; k0 += 32) {
        // ---- fill As: 128x32 = 1024 float4, 4 per thread ----
#pragma unroll
        for (int i = 0; i < 4; i++) {
            int f4 = tid + i * 256;
            int r = f4 >> 3, c4 = (f4 & 7) * 4;
            int gr = rowBase + r;
            float4 v = make_float4(0.f, 0.f, 0.f, 0.f);
            if (gr < M) v = *(const float4*)&A[(size_t)gr * K + k0 + c4];
            As[r][c4 + 0] = __uint_as_float(f2tf32(v.x));
            As[r][c4 + 1] = __uint_as_float(f2tf32(v.y));
            As[r][c4 + 2] = __uint_as_float(f2tf32(v.z));
            As[r][c4 + 3] = __uint_as_float(f2tf32(v.w));
        }
        // ---- fill Bs: 32x64 = 512 float4, 2 per thread ----
#pragma unroll
        for (int i = 0; i < 2; i++) {
            int f4 = tid + i * 256;
            int r = f4 >> 4, c4 = (f4 & 15) * 4;
            float4 v = *(const float4*)&B[(size_t)(k0 + r) * N + colBase + c4];
            Bs[r][c4 + 0] = __uint_as_float(f2tf32(v.x));
            Bs[r][c4 + 1] = __uint_as_float(f2tf32(v.y));
            Bs[r][c4 + 2] = __uint_as_float(f2tf32(v.z));
            Bs[r][c4 + 3] = __uint_as_float(f2tf32(v.w));
        }
        __syncthreads();

#pragma unroll
        for (int ks = 0; ks < 4; ks++) {
            int kk = ks * 8;
            unsigned int af[2][4], bf[4][2];
#pragma unroll
            for (int mi = 0; mi < 2; mi++) {
                int m = wm + mi * 16 + mrow;
                af[mi][0] = __float_as_uint(As[m][kk + kcol]);
                af[mi][1] = __float_as_uint(As[m + 8][kk + kcol]);
                af[mi][2] = __float_as_uint(As[m][kk + kcol + 4]);
                af[mi][3] = __float_as_uint(As[m + 8][kk + kcol + 4]);
            }
#pragma unroll
            for (int ni = 0; ni < 4; ni++) {
                int nn = wn + ni * 8 + mrow;
                bf[ni][0] = __float_as_uint(Bs[kk + kcol][nn]);
                bf[ni][1] = __float_as_uint(Bs[kk + kcol + 4][nn]);
            }
#pragma unroll
            for (int mi = 0; mi < 2; mi++)
#pragma unroll
                for (int ni = 0; ni < 4; ni++) {
                    asm volatile(
                        "mma.sync.aligned.m16n8k8.row.col.f32.tf32.tf32.f32 "
                        "{%0,%1,%2,%3},{%4,%5,%6,%7},{%8,%9},{%0,%1,%2,%3};"
                        : "+f"(acc[mi][ni][0]), "+f"(acc[mi][ni][1]),
                          "+f"(acc[mi][ni][2]), "+f"(acc[mi][ni][3])
                        : "r"(af[mi][0]), "r"(af[mi][1]), "r"(af[mi][2]), "r"(af[mi][3]),
                          "r"(bf[ni][0]), "r"(bf[ni][1]));
                }
        }
        __syncthreads();
    }

    // ---- epilogue ----
#pragma unroll
    for (int mi = 0; mi < 2; mi++) {
        int r0 = rowBase + wm + mi * 16 + mrow;
#pragma unroll
        for (int ni = 0; ni < 4; ni++) {
            int c = colBase + wn + ni * 8 + kcol * 2;
            if (r0 < M) {
                C[(size_t)r0 * N + c]     = acc[mi][ni][0];
                C[(size_t)r0 * N + c + 1] = acc[mi][ni][1];
            }
            if (r0 + 8 < M) {
                C[(size_t)(r0 + 8) * N + c]     = acc[mi][ni][2];
                C[(size_t)(r0 + 8) * N + c + 1] = acc[mi][ni][3];
            }
        }
    }
}

// ---------------- fallback SGEMM (small classifier GEMMs) ---------------------
#define BM 128
#define BN 64
#define BK 16
#define TM 8
#define TN 4
__global__ __launch_bounds__(256) void sgemm_k(
    const float* __restrict__ A, const float* __restrict__ B,
    float* __restrict__ C, int M, int N, int K,
    const float* __restrict__ bias, int relu)
{
    __shared__ float As[BK][BM];
    __shared__ float Bs[BK][BN];
    int tid = threadIdx.x;
    int tx = tid % (BN / TN);
    int ty = tid / (BN / TN);
    int rowBase = blockIdx.y * BM;
    int colBase = blockIdx.x * BN;

    float acc[TM][TN];
#pragma unroll
    for (int i = 0; i < TM; i++)
#pragma unroll
        for (int j = 0; j < TN; j++) acc[i][j] = 0.f;

    for (int k0 = 0; k0 < K; k0 += BK) {
        for (int i = tid; i < BM * BK; i += 256) {
            int r = i / BK, c = i % BK;
            int gr = rowBase + r, gc = k0 + c;
            As[c][r] = (gr < M && gc < K) ? A[(size_t)gr * K + gc] : 0.f;
        }
        for (int i = tid; i < BK * BN; i += 256) {
            int r = i / BN, c = i % BN;
            int gr = k0 + r, gc = colBase + c;
            Bs[r][c] = (gr < K && gc < N) ? B[(size_t)gr * N + gc] : 0.f;
        }
        __syncthreads();
#pragma unroll
        for (int k = 0; k < BK; k++) {
            float a[TM], b[TN];
#pragma unroll
            for (int i = 0; i < TM; i++) a[i] = As[k][ty * TM + i];
#pragma unroll
            for (int j = 0; j < TN; j++) b[j] = Bs[k][tx * TN + j];
#pragma unroll
            for (int i = 0; i < TM; i++)
#pragma unroll
                for (int j = 0; j < TN; j++) acc[i][j] += a[i] * b[j];
        }
        __syncthreads();
    }
#pragma unroll
    for (int i = 0; i < TM; i++) {
        int gr = rowBase + ty * TM + i;
        if (gr >= M) continue;
#pragma unroll
        for (int j = 0; j < TN; j++) {
            int gc = colBase + tx * TN + j;
            if (gc >= N) continue;
            float v = acc[i][j];
            if (bias) v += bias[gc];
            if (relu) v = fmaxf(v, 0.f);
            C[(size_t)gr * N + gc] = v;
        }
    }
}

// ---------------- attention coefficients: a_s[n,h], a_d[n,h] ------------------
__global__ void attn_coef_k(const float* __restrict__ h,
                            const float* __restrict__ asw,
                            const float* __restrict__ adw,
                            float* __restrict__ as_o, float* __restrict__ ad_o,
                            int n, int H)
{
    int w = (blockIdx.x * blockDim.x + threadIdx.x) >> 5;
    int lane = threadIdx.x & 31;
    if (w >= n * H) return;
    int node = w / H, hd = w - node * H;
    const float* row = h + (size_t)node * H * CDIM + hd * CDIM;
    float s = 0.f, d = 0.f;
#pragma unroll
    for (int c = lane; c < CDIM; c += 32) {
        float v = row[c];
        s += v * asw[hd * CDIM + c];
        d += v * adw[hd * CDIM + c];
    }
#pragma unroll
    for (int o = 16; o; o >>= 1) {
        s += __shfl_down_sync(0xFFFFFFFFu, s, o);
        d += __shfl_down_sync(0xFFFFFFFFu, d, o);
    }
    if (!lane) { as_o[w] = s; ad_o[w] = d; }
}

// ---------------- segment max over dst ----------------------------------------
__global__ void edge_max_k(const int* __restrict__ src, const int* __restrict__ dst,
                           const float* __restrict__ as_o, const float* __restrict__ ad_o,
                           float* emax, int E, int et, int H)
{
    int idx = blockIdx.x * blockDim.x + threadIdx.x;
    if (idx >= et * H) return;
    int e = idx / H, hd = idx - e * H;
    int s, d;
    if (e < E) { s = src[e]; d = dst[e]; } else { s = d = e - E; }
    float v = as_o[s * H + hd] + ad_o[d * H + hd];
    v = v > 0.f ? v : 0.2f * v;
    atomicMaxF(&emax[d * H + hd], v);
}

// ---------------- exp(e - max) + segment sum ----------------------------------
__global__ void edge_exp_k(const int* __restrict__ src, const int* __restrict__ dst,
                           const float* __restrict__ as_o, const float* __restrict__ ad_o,
                           const float* __restrict__ emax, float* den, float* ex,
                           int E, int et, int H)
{
    int idx = blockIdx.x * blockDim.x + threadIdx.x;
    if (idx >= et * H) return;
    int e = idx / H, hd = idx - e * H;
    int s, d;
    if (e < E) { s = src[e]; d = dst[e]; } else { s = d = e - E; }
    float v = as_o[s * H + hd] + ad_o[d * H + hd];
    v = v > 0.f ? v : 0.2f * v;
    float ev = expf(v - emax[d * H + hd]);
    ex[idx] = ev;
    atomicAdd(&den[d * H + hd], ev);
}

// ---------------- message scatter: out[dst] += alpha * h[src] -----------------
template <int H>
__global__ void scatter_k(const int* __restrict__ src, const int* __restrict__ dst,
                          const float* __restrict__ h, const float* __restrict__ ex,
                          const float* __restrict__ den, float* __restrict__ out,
                          int E, int et)
{
    int w = (blockIdx.x * blockDim.x + threadIdx.x) >> 5;
    int lane = threadIdx.x & 31;
    if (w >= et) return;
    int s, d;
    if (w < E) { s = src[w]; d = dst[w]; } else { s = d = w - E; }
    float a = 0.f;
    if (lane < H) a = ex[(size_t)w * H + lane] / den[d * H + lane];
    const float4* hr4 = (const float4*)(h + (size_t)s * H * CDIM);
    float*        od  = out + (size_t)d * H * CDIM;
    const int NV = H * CDIM / 4;
#pragma unroll
    for (int k = 0; k < NV; k += 32) {
        int idx = k + lane;
        if (idx < NV) {
            int head = idx / (CDIM / 4);
            float al = __shfl_sync(0xFFFFFFFFu, a, head);
            float4 v = hr4[idx];
            v.x *= al; v.y *= al; v.z *= al; v.w *= al;
            redAdd4(od + idx * 4, v);
        }
    }
}

// ---------------- batch norm (C=256 channels) ---------------------------------
__global__ void bn_stats_k(const float* __restrict__ x, int n, float* sum, float* sq) {
    int ch = threadIdx.x;
    float s = 0.f, s2 = 0.f;
    for (int r = blockIdx.x; r < n; r += gridDim.x) {
        float v = x[(size_t)r * HWID + ch];
        s += v; s2 += v * v;
    }
    atomicAdd(&sum[ch], s);
    atomicAdd(&sq[ch], s2);
}

__global__ void bn_fin_k(const float* sum, const float* sq,
                         const float* __restrict__ g, const float* __restrict__ be,
                         int n, float* scl, float* sft) {
    int ch = threadIdx.x;
    float mu = sum[ch] / (float)n;
    float var = fmaxf(sq[ch] / (float)n - mu * mu, 0.f);
    float r = rsqrtf(var + 1e-5f);
    float s = g[ch] * r;
    scl[ch] = s;
    sft[ch] = be[ch] - mu * s;
}

__global__ void bn_apply_elu_k(const float4* __restrict__ in, float4* __restrict__ outp,
                               const float* __restrict__ scl, const float* __restrict__ sft,
                               int n4) {
    int i = blockIdx.x * blockDim.x + threadIdx.x;
    if (i >= n4) return;
    int c4 = (i & (HWID / 4 - 1)) * 4;
    float4 v = in[i];
    v.x = v.x * scl[c4 + 0] + sft[c4 + 0];
    v.y = v.y * scl[c4 + 1] + sft[c4 + 1];
    v.z = v.z * scl[c4 + 2] + sft[c4 + 2];
    v.w = v.w * scl[c4 + 3] + sft[c4 + 3];
    v.x = v.x > 0.f ? v.x : expm1f(v.x);
    v.y = v.y > 0.f ? v.y : expm1f(v.y);
    v.z = v.z > 0.f ? v.z : expm1f(v.z);
    v.w = v.w > 0.f ? v.w : expm1f(v.w);
    outp[i] = v;
}

// ---------------- host-side orchestration -------------------------------------
static void run_tf32gemm(const float* A, const float* B, float* C, int M, int N, int K) {
    dim3 grid(N / 64, (M + 127) / 128);
    tf32gemm_k<<<grid, 256>>>(A, B, C, M, N, K);
}

static void run_sgemm(const float* A, const float* B, float* C, int M, int N, int K,
                      const float* bias, int relu) {
    dim3 grid((N + BN - 1) / BN, (M + BM - 1) / BM);
    sgemm_k<<<grid, 256>>>(A, B, C, M, N, K, bias, relu);
}

static void gat_aggregate(const int* src, const int* dst,
                          const float* h, const float* asw, const float* adw,
                          float* asb, float* adb, float* emaxb, float* denb, float* exb,
                          float* aggout, int n, int H)
{
    int nh = n * H;
    attn_coef_k<<<(nh * 32 + 255) / 256, 256>>>(h, asw, adw, asb, adb, n, H);
    fill_k<<<(nh + 255) / 256, 256>>>(emaxb, -3.4e38f, nh);
    fill_k<<<(nh + 255) / 256, 256>>>(denb, 0.f, nh);
    int tot4 = n * H * CDIM / 4;
    fill4_k<<<(tot4 + 255) / 256, 256>>>((float4*)aggout, 0.f, tot4);
    int etH = ET_EDGES * H;
    edge_max_k<<<(etH + 255) / 256, 256>>>(src, dst, asb, adb, emaxb, N_EDGES, ET_EDGES, H);
    edge_exp_k<<<(etH + 255) / 256, 256>>>(src, dst, asb, adb, emaxb, denb, exb, N_EDGES, ET_EDGES, H);
    long long thr = (long long)ET_EDGES * 32;
    int blocks = (int)((thr + 255) / 256);
    if (H == 4)
        scatter_k<4><<<blocks, 256>>>(src, dst, h, exb, denb, aggout, N_EDGES, ET_EDGES);
    else
        scatter_k<1><<<blocks, 256>>>(src, dst, h, exb, denb, aggout, N_EDGES, ET_EDGES);
}

static void bn_elu(const float* in, float* outp, const float* g, const float* be, int n,
                   float* sumb, float* sqb, float* sclb, float* sftb)
{
    fill_k<<<1, 256>>>(sumb, 0.f, HWID);
    fill_k<<<1, 256>>>(sqb, 0.f, HWID);
    bn_stats_k<<<512, 256>>>(in, n, sumb, sqb);
    bn_fin_k<<<1, 256>>>(sumb, sqb, g, be, n, sclb, sftb);
    bn_apply_elu_k<<<(n * HWID / 4 + 255) / 256, 256>>>(
        (const float4*)in, (float4*)outp, sclb, sftb, n * HWID / 4);
}

extern "C" void kernel_launch(void* const* d_in, const int* in_sizes, int n_in,
                              void* d_out, int out_size)
{
    const float* x   = (const float*)d_in[0];
    const int*   ei  = (const int*)  d_in[1];
    const float* W0  = (const float*)d_in[2];
    const float* as0 = (const float*)d_in[3];
    const float* ad0 = (const float*)d_in[4];
    // b0 (d_in[5]) cancels through BatchNorm — skipped
    const float* W1  = (const float*)d_in[6];
    const float* as1 = (const float*)d_in[7];
    const float* ad1 = (const float*)d_in[8];
    // b1 (d_in[9]) cancels through BatchNorm — skipped
    const float* W2  = (const float*)d_in[10];
    const float* as2 = (const float*)d_in[11];
    const float* ad2 = (const float*)d_in[12];
    const float* b2  = (const float*)d_in[13];
    const float* g0  = (const float*)d_in[14];
    const float* be0 = (const float*)d_in[15];
    const float* g1  = (const float*)d_in[16];
    const float* be1 = (const float*)d_in[17];
    const float* Wc1 = (const float*)d_in[18];
    const float* bc1 = (const float*)d_in[19];
    const float* Wc2 = (const float*)d_in[20];
    const float* bc2 = (const float*)d_in[21];
    float* out = (float*)d_out;

    const int n = N_NODES;
    const int* src = ei;
    const int* dst = ei + N_EDGES;

    float *hbuf, *aggbuf, *asb, *adb, *emaxb, *denb, *exb;
    float *sumb, *sqb, *sclb, *sftb, *clsb;
    cudaGetSymbolAddress((void**)&hbuf,  g_h);
    cudaGetSymbolAddress((void**)&aggbuf, g_agg);
    cudaGetSymbolAddress((void**)&asb,   g_as);
    cudaGetSymbolAddress((void**)&adb,   g_ad);
    cudaGetSymbolAddress((void**)&emaxb, g_emax);
    cudaGetSymbolAddress((void**)&denb,  g_den);
    cudaGetSymbolAddress((void**)&exb,   g_ex);
    cudaGetSymbolAddress((void**)&sumb,  g_sum);
    cudaGetSymbolAddress((void**)&sqb,   g_sq);
    cudaGetSymbolAddress((void**)&sclb,  g_scl);
    cudaGetSymbolAddress((void**)&sftb,  g_sft);
    cudaGetSymbolAddress((void**)&clsb,  g_cls);

    // ---- GAT layer 0: 128 -> 4x64 (concat) ----
    run_tf32gemm(x, W0, hbuf, n, 256, 128);
    gat_aggregate(src, dst, hbuf, as0, ad0, asb, adb, emaxb, denb, exb, aggbuf, n, 4);
    bn_elu(aggbuf, hbuf, g0, be0, n, sumb, sqb, sclb, sftb);

    // ---- GAT layer 1: 256 -> 4x64 (concat) ----
    run_tf32gemm(hbuf, W1, aggbuf, n, 256, 256);
    gat_aggregate(src, dst, aggbuf, as1, ad1, asb, adb, emaxb, denb, exb, hbuf, n, 4);
    bn_elu(hbuf, aggbuf, g1, be1, n, sumb, sqb, sclb, sftb);

    // ---- GAT layer 2: 256 -> 1x64 ----
    run_tf32gemm(aggbuf, W2, hbuf, n, 64, 256);
    gat_aggregate(src, dst, hbuf, as2, ad2, asb, adb, emaxb, denb, exb, aggbuf, n, 1);
    addbias_k<<<(n * 64 + 255) / 256, 256>>>(aggbuf, b2, n * 64, 64);

    // ---- classifier: 64 -> 32 (relu) -> 2 ----
    run_sgemm(aggbuf, Wc1, clsb, n, 32, 64, bc1, 1);
    run_sgemm(clsb, Wc2, out, n, 2, 32, bc2, 0);
}

// round 4
// speedup vs baseline: 1.6088x; 1.1579x over previous
#include <cuda_runtime.h>
#include <math.h>

// Problem constants (fixed by the dataset)
#define N_NODES 50000
#define N_EDGES 800000
#define ET_EDGES (N_NODES + N_EDGES)   // edges + self loops
#define HWID 256                        // heads*hid for layers 0/1
#define CDIM 64
#define NBLK_SCAN ((N_NODES + 255) / 256)   // 196

// ---------------- scratch (device globals; no allocation allowed) -------------
static __device__ float g_h   [(size_t)N_NODES * HWID];
static __device__ float g_agg [(size_t)N_NODES * HWID];
static __device__ float g_as  [N_NODES * 4];
static __device__ float g_ad  [N_NODES * 4];
static __device__ float g_emax[N_NODES * 4];
static __device__ float g_den [N_NODES * 4];
static __device__ float g_ex  [(size_t)ET_EDGES * 4];
static __device__ float g_sum [HWID];
static __device__ float g_sq  [HWID];
static __device__ float g_scl [HWID];
static __device__ float g_sft [HWID];
static __device__ float g_cls [N_NODES * 32];
// CSR scratch
static __device__ int g_deg   [N_NODES];
static __device__ int g_cursor[N_NODES];
static __device__ int g_rowptr[N_NODES + 1];
static __device__ int g_eidx  [ET_EDGES];
static __device__ int g_blksum[256];

// ---------------- helpers -----------------------------------------------------
__device__ __forceinline__ void atomicMaxF(float* addr, float v) {
    if (v >= 0.f) atomicMax((int*)addr, __float_as_int(v));
    else          atomicMin((unsigned int*)addr, (unsigned int)__float_as_int(v));
}

__device__ __forceinline__ unsigned int f2tf32(float f) {
    unsigned int u;
    asm("cvt.rna.tf32.f32 %0, %1;" : "=r"(u) : "f"(f));
    return u;
}

__global__ void fill_k(float* p, float v, int n) {
    int i = blockIdx.x * blockDim.x + threadIdx.x;
    if (i < n) p[i] = v;
}

__global__ void filli_k(int* p, int n) {
    int i = blockIdx.x * blockDim.x + threadIdx.x;
    if (i < n) p[i] = 0;
}

// ---------------- CSR construction --------------------------------------------
__global__ void deg_k(const int* __restrict__ dst, int* deg, int E, int et) {
    int e = blockIdx.x * blockDim.x + threadIdx.x;
    if (e >= et) return;
    int d = e < E ? dst[e] : e - E;
    atomicAdd(&deg[d], 1);
}

__global__ void scan_part_k(const int* __restrict__ deg, int* rowptr, int* blksum, int n) {
    __shared__ int sm[256];
    int i = blockIdx.x * 256 + threadIdx.x;
    int v = (i < n) ? deg[i] : 0;
    sm[threadIdx.x] = v;
    __syncthreads();
    for (int o = 1; o < 256; o <<= 1) {
        int t = (threadIdx.x >= o) ? sm[threadIdx.x - o] : 0;
        __syncthreads();
        sm[threadIdx.x] += t;
        __syncthreads();
    }
    if (i < n) rowptr[i] = sm[threadIdx.x] - v;      // exclusive
    if (threadIdx.x == 255) blksum[blockIdx.x] = sm[255];
}

__global__ void scan_tops_k(int* blksum, int nb) {
    __shared__ int sm[256];
    int v = (threadIdx.x < nb) ? blksum[threadIdx.x] : 0;
    sm[threadIdx.x] = v;
    __syncthreads();
    for (int o = 1; o < 256; o <<= 1) {
        int t = (threadIdx.x >= o) ? sm[threadIdx.x - o] : 0;
        __syncthreads();
        sm[threadIdx.x] += t;
        __syncthreads();
    }
    if (threadIdx.x < nb) blksum[threadIdx.x] = sm[threadIdx.x] - v;   // exclusive
}

__global__ void scan_write_k(int* rowptr, const int* __restrict__ blksum, int n) {
    int i = blockIdx.x * 256 + threadIdx.x;
    if (i < n) rowptr[i] += blksum[blockIdx.x];
    if (i == 0) rowptr[n] = ET_EDGES;
}

__global__ void fill_pos_k(const int* __restrict__ dst, const int* __restrict__ rowptr,
                           int* cursor, int* eidx, int E, int et) {
    int e = blockIdx.x * blockDim.x + threadIdx.x;
    if (e >= et) return;
    int d = e < E ? dst[e] : e - E;
    int p = atomicAdd(&cursor[d], 1);
    eidx[rowptr[d] + p] = e;
}

// ---------------- 3xTF32 tensor-core GEMM: C = A @ B (fp32-accurate) ----------
// BM=128, BN=64, BK=32; 256 threads = 8 warps (4x2), warp tile 32x32.
// Requires: K % 32 == 0, N % 64 == 0. Dynamic smem = 55296 bytes.
__global__ __launch_bounds__(256) void tf32gemm3_k(
    const float* __restrict__ A, const float* __restrict__ B,
    float* __restrict__ C, int M, int N, int K)
{
    extern __shared__ float smem[];
    float (*Ah)[36] = (float(*)[36])(smem);                 // 128*36
    float (*Al)[36] = (float(*)[36])(smem + 4608);          // 128*36
    float (*Bh)[72] = (float(*)[72])(smem + 9216);          // 32*72
    float (*Bl)[72] = (float(*)[72])(smem + 11520);         // 32*72

    int tid = threadIdx.x;
    int warp = tid >> 5, lane = tid & 31;
    int wm = (warp & 3) * 32;
    int wn = (warp >> 2) * 32;
    int rowBase = blockIdx.y * 128;
    int colBase = blockIdx.x * 64;
    int mrow = lane >> 2;           // 0..7
    int kcol = lane & 3;            // 0..3

    float acc[2][4][4];
#pragma unroll
    for (int mi = 0; mi < 2; mi++)
#pragma unroll
        for (int ni = 0; ni < 4; ni++)
#pragma unroll
            for (int r = 0; r < 4; r++) acc[mi][ni][r] = 0.f;

    for (int k0 = 0; k0 < K; k0 += 32) {
#pragma unroll
        for (int i = 0; i < 4; i++) {
            int f4 = tid + i * 256;
            int r = f4 >> 3, c4 = (f4 & 7) * 4;
            int gr = rowBase + r;
            float4 v = make_float4(0.f, 0.f, 0.f, 0.f);
            if (gr < M) v = *(const float4*)&A[(size_t)gr * K + k0 + c4];
            float hx = __uint_as_float(f2tf32(v.x));
            float hy = __uint_as_float(f2tf32(v.y));
            float hz = __uint_as_float(f2tf32(v.z));
            float hw = __uint_as_float(f2tf32(v.w));
            Ah[r][c4 + 0] = hx; Al[r][c4 + 0] = __uint_as_float(f2tf32(v.x - hx));
            Ah[r][c4 + 1] = hy; Al[r][c4 + 1] = __uint_as_float(f2tf32(v.y - hy));
            Ah[r][c4 + 2] = hz; Al[r][c4 + 2] = __uint_as_float(f2tf32(v.z - hz));
            Ah[r][c4 + 3] = hw; Al[r][c4 + 3] = __uint_as_float(f2tf32(v.w - hw));
        }
#pragma unroll
        for (int i = 0; i < 2; i++) {
            int f4 = tid + i * 256;
            int r = f4 >> 4, c4 = (f4 & 15) * 4;
            float4 v = *(const float4*)&B[(size_t)(k0 + r) * N + colBase + c4];
            float hx = __uint_as_float(f2tf32(v.x));
            float hy = __uint_as_float(f2tf32(v.y));
            float hz = __uint_as_float(f2tf32(v.z));
            float hw = __uint_as_float(f2tf32(v.w));
            Bh[r][c4 + 0] = hx; Bl[r][c4 + 0] = __uint_as_float(f2tf32(v.x - hx));
            Bh[r][c4 + 1] = hy; Bl[r][c4 + 1] = __uint_as_float(f2tf32(v.y - hy));
            Bh[r][c4 + 2] = hz; Bl[r][c4 + 2] = __uint_as_float(f2tf32(v.z - hz));
            Bh[r][c4 + 3] = hw; Bl[r][c4 + 3] = __uint_as_float(f2tf32(v.w - hw));
        }
        __syncthreads();

#pragma unroll
        for (int ks = 0; ks < 4; ks++) {
            int kk = ks * 8;
            unsigned int ah[2][4], al[2][4], bh[4][2], bl[4][2];
#pragma unroll
            for (int mi = 0; mi < 2; mi++) {
                int m = wm + mi * 16 + mrow;
                ah[mi][0] = __float_as_uint(Ah[m][kk + kcol]);
                ah[mi][1] = __float_as_uint(Ah[m + 8][kk + kcol]);
                ah[mi][2] = __float_as_uint(Ah[m][kk + kcol + 4]);
                ah[mi][3] = __float_as_uint(Ah[m + 8][kk + kcol + 4]);
                al[mi][0] = __float_as_uint(Al[m][kk + kcol]);
                al[mi][1] = __float_as_uint(Al[m + 8][kk + kcol]);
                al[mi][2] = __float_as_uint(Al[m][kk + kcol + 4]);
                al[mi][3] = __float_as_uint(Al[m + 8][kk + kcol + 4]);
            }
#pragma unroll
            for (int ni = 0; ni < 4; ni++) {
                int nn = wn + ni * 8 + mrow;
                bh[ni][0] = __float_as_uint(Bh[kk + kcol][nn]);
                bh[ni][1] = __float_as_uint(Bh[kk + kcol + 4][nn]);
                bl[ni][0] = __float_as_uint(Bl[kk + kcol][nn]);
                bl[ni][1] = __float_as_uint(Bl[kk + kcol + 4][nn]);
            }
#define MMA_T(ar, br, mi, ni)                                                     \
    asm volatile(                                                                 \
        "mma.sync.aligned.m16n8k8.row.col.f32.tf32.tf32.f32 "                     \
        "{%0,%1,%2,%3},{%4,%5,%6,%7},{%8,%9},{%0,%1,%2,%3};"                      \
        : "+f"(acc[mi][ni][0]), "+f"(acc[mi][ni][1]),                             \
          "+f"(acc[mi][ni][2]), "+f"(acc[mi][ni][3])                              \
        : "r"(ar[mi][0]), "r"(ar[mi][1]), "r"(ar[mi][2]), "r"(ar[mi][3]),         \
          "r"(br[ni][0]), "r"(br[ni][1]))
#pragma unroll
            for (int mi = 0; mi < 2; mi++)
#pragma unroll
                for (int ni = 0; ni < 4; ni++) {
                    MMA_T(ah, bl, mi, ni);
                    MMA_T(al, bh, mi, ni);
                    MMA_T(ah, bh, mi, ni);
                }
#undef MMA_T
        }
        __syncthreads();
    }

#pragma unroll
    for (int mi = 0; mi < 2; mi++) {
        int r0 = rowBase + wm + mi * 16 + mrow;
#pragma unroll
        for (int ni = 0; ni < 4; ni++) {
            int c = colBase + wn + ni * 8 + kcol * 2;
            if (r0 < M) {
                C[(size_t)r0 * N + c]     = acc[mi][ni][0];
                C[(size_t)r0 * N + c + 1] = acc[mi][ni][1];
            }
            if (r0 + 8 < M) {
                C[(size_t)(r0 + 8) * N + c]     = acc[mi][ni][2];
                C[(size_t)(r0 + 8) * N + c + 1] = acc[mi][ni][3];
            }
        }
    }
}

// ---------------- fallback SGEMM (small classifier GEMMs) ---------------------
#define BM 128
#define BN 64
#define BK 16
#define TM 8
#define TN 4
__global__ __launch_bounds__(256) void sgemm_k(
    const float* __restrict__ A, const float* __restrict__ B,
    float* __restrict__ C, int M, int N, int K,
    const float* __restrict__ bias, int relu)
{
    __shared__ float As[BK][BM];
    __shared__ float Bs[BK][BN];
    int tid = threadIdx.x;
    int tx = tid % (BN / TN);
    int ty = tid / (BN / TN);
    int rowBase = blockIdx.y * BM;
    int colBase = blockIdx.x * BN;

    float acc[TM][TN];
#pragma unroll
    for (int i = 0; i < TM; i++)
#pragma unroll
        for (int j = 0; j < TN; j++) acc[i][j] = 0.f;

    for (int k0 = 0; k0 < K; k0 += BK) {
        for (int i = tid; i < BM * BK; i += 256) {
            int r = i / BK, c = i % BK;
            int gr = rowBase + r, gc = k0 + c;
            As[c][r] = (gr < M && gc < K) ? A[(size_t)gr * K + gc] : 0.f;
        }
        for (int i = tid; i < BK * BN; i += 256) {
            int r = i / BN, c = i % BN;
            int gr = k0 + r, gc = colBase + c;
            Bs[r][c] = (gr < K && gc < N) ? B[(size_t)gr * N + gc] : 0.f;
        }
        __syncthreads();
#pragma unroll
        for (int k = 0; k < BK; k++) {
            float a[TM], b[TN];
#pragma unroll
            for (int i = 0; i < TM; i++) a[i] = As[k][ty * TM + i];
#pragma unroll
            for (int j = 0; j < TN; j++) b[j] = Bs[k][tx * TN + j];
#pragma unroll
            for (int i = 0; i < TM; i++)
#pragma unroll
                for (int j = 0; j < TN; j++) acc[i][j] += a[i] * b[j];
        }
        __syncthreads();
    }
#pragma unroll
    for (int i = 0; i < TM; i++) {
        int gr = rowBase + ty * TM + i;
        if (gr >= M) continue;
#pragma unroll
        for (int j = 0; j < TN; j++) {
            int gc = colBase + tx * TN + j;
            if (gc >= N) continue;
            float v = acc[i][j];
            if (bias) v += bias[gc];
            if (relu) v = fmaxf(v, 0.f);
            C[(size_t)gr * N + gc] = v;
        }
    }
}

// ---------------- attention coefficients: a_s[n,h], a_d[n,h] ------------------
__global__ void attn_coef_k(const float* __restrict__ h,
                            const float* __restrict__ asw,
                            const float* __restrict__ adw,
                            float* __restrict__ as_o, float* __restrict__ ad_o,
                            int n, int H)
{
    int w = (blockIdx.x * blockDim.x + threadIdx.x) >> 5;
    int lane = threadIdx.x & 31;
    if (w >= n * H) return;
    int node = w / H, hd = w - node * H;
    const float* row = h + (size_t)node * H * CDIM + hd * CDIM;
    float s = 0.f, d = 0.f;
#pragma unroll
    for (int c = lane; c < CDIM; c += 32) {
        float v = row[c];
        s += v * asw[hd * CDIM + c];
        d += v * adw[hd * CDIM + c];
    }
#pragma unroll
    for (int o = 16; o; o >>= 1) {
        s += __shfl_down_sync(0xFFFFFFFFu, s, o);
        d += __shfl_down_sync(0xFFFFFFFFu, d, o);
    }
    if (!lane) { as_o[w] = s; ad_o[w] = d; }
}

// ---------------- segment max over dst ----------------------------------------
__global__ void edge_max_k(const int* __restrict__ src, const int* __restrict__ dst,
                           const float* __restrict__ as_o, const float* __restrict__ ad_o,
                           float* emax, int E, int et, int H)
{
    int idx = blockIdx.x * blockDim.x + threadIdx.x;
    if (idx >= et * H) return;
    int e = idx / H, hd = idx - e * H;
    int s, d;
    if (e < E) { s = src[e]; d = dst[e]; } else { s = d = e - E; }
    float v = as_o[s * H + hd] + ad_o[d * H + hd];
    v = v > 0.f ? v : 0.2f * v;
    atomicMaxF(&emax[d * H + hd], v);
}

// ---------------- exp(e - max) + segment sum ----------------------------------
__global__ void edge_exp_k(const int* __restrict__ src, const int* __restrict__ dst,
                           const float* __restrict__ as_o, const float* __restrict__ ad_o,
                           const float* __restrict__ emax, float* den, float* ex,
                           int E, int et, int H)
{
    int idx = blockIdx.x * blockDim.x + threadIdx.x;
    if (idx >= et * H) return;
    int e = idx / H, hd = idx - e * H;
    int s, d;
    if (e < E) { s = src[e]; d = dst[e]; } else { s = d = e - E; }
    float v = as_o[s * H + hd] + ad_o[d * H + hd];
    v = v > 0.f ? v : 0.2f * v;
    float ev = expf(v - emax[d * H + hd]);
    ex[idx] = ev;
    atomicAdd(&den[d * H + hd], ev);
}

// ---------------- CSR aggregation (gather): out[d] = sum alpha*h[src] ---------
// H=4: one warp per dst node; 256 channels = 2 float4 per lane
__global__ void agg4_k(const int* __restrict__ rowptr, const int* __restrict__ eidx,
                       const int* __restrict__ src, const float* __restrict__ h,
                       const float* __restrict__ ex, const float* __restrict__ den,
                       float* __restrict__ out, int n, int E)
{
    int w = (blockIdx.x * blockDim.x + threadIdx.x) >> 5;
    int lane = threadIdx.x & 31;
    if (w >= n) return;
    int beg = rowptr[w], end = rowptr[w + 1];
    float4 dn = *(const float4*)&den[(size_t)w * 4];
    float i0 = 1.f / dn.x, i1 = 1.f / dn.y, i2 = 1.f / dn.z, i3 = 1.f / dn.w;
    float4 acc0 = make_float4(0.f, 0.f, 0.f, 0.f);
    float4 acc1 = make_float4(0.f, 0.f, 0.f, 0.f);
    int hsel = lane >> 4;   // 0 for lanes 0-15, 1 for lanes 16-31
    for (int j = beg; j < end; j++) {
        int e = eidx[j];
        int s = e < E ? src[e] : e - E;
        float4 ex4 = *(const float4*)&ex[(size_t)e * 4];
        float aA = hsel ? ex4.y * i1 : ex4.x * i0;
        float aB = hsel ? ex4.w * i3 : ex4.z * i2;
        const float4* hr = (const float4*)(h + (size_t)s * 256);
        float4 v0 = hr[lane];
        float4 v1 = hr[32 + lane];
        acc0.x += v0.x * aA; acc0.y += v0.y * aA; acc0.z += v0.z * aA; acc0.w += v0.w * aA;
        acc1.x += v1.x * aB; acc1.y += v1.y * aB; acc1.z += v1.z * aB; acc1.w += v1.w * aB;
    }
    float4* o4 = (float4*)(out + (size_t)w * 256);
    o4[lane] = acc0;
    o4[32 + lane] = acc1;
}

// H=1: one warp per dst node; 64 channels = 1 float4 on lanes 0-15; +bias
__global__ void agg1_k(const int* __restrict__ rowptr, const int* __restrict__ eidx,
                       const int* __restrict__ src, const float* __restrict__ h,
                       const float* __restrict__ ex, const float* __restrict__ den,
                       const float* __restrict__ bias,
                       float* __restrict__ out, int n, int E)
{
    int w = (blockIdx.x * blockDim.x + threadIdx.x) >> 5;
    int lane = threadIdx.x & 31;
    if (w >= n) return;
    int beg = rowptr[w], end = rowptr[w + 1];
    float inv = 1.f / den[w];
    float4 acc = make_float4(0.f, 0.f, 0.f, 0.f);
    for (int j = beg; j < end; j++) {
        int e = eidx[j];
        int s = e < E ? src[e] : e - E;
        float a = ex[e] * inv;
        if (lane < 16) {
            float4 v = ((const float4*)(h + (size_t)s * 64))[lane];
            acc.x += v.x * a; acc.y += v.y * a; acc.z += v.z * a; acc.w += v.w * a;
        }
    }
    if (lane < 16) {
        float4 b4 = ((const float4*)bias)[lane];
        acc.x += b4.x; acc.y += b4.y; acc.z += b4.z; acc.w += b4.w;
        ((float4*)(out + (size_t)w * 64))[lane] = acc;
    }
}

// ---------------- batch norm (C=256 channels) ---------------------------------
__global__ void bn_stats_k(const float* __restrict__ x, int n, float* sum, float* sq) {
    int ch = threadIdx.x;
    float s = 0.f, s2 = 0.f;
    for (int r = blockIdx.x; r < n; r += gridDim.x) {
        float v = x[(size_t)r * HWID + ch];
        s += v; s2 += v * v;
    }
    atomicAdd(&sum[ch], s);
    atomicAdd(&sq[ch], s2);
}

__global__ void bn_fin_k(const float* sum, const float* sq,
                         const float* __restrict__ g, const float* __restrict__ be,
                         int n, float* scl, float* sft) {
    int ch = threadIdx.x;
    float mu = sum[ch] / (float)n;
    float var = fmaxf(sq[ch] / (float)n - mu * mu, 0.f);
    float r = rsqrtf(var + 1e-5f);
    float s = g[ch] * r;
    scl[ch] = s;
    sft[ch] = be[ch] - mu * s;
}

__global__ void bn_apply_elu_k(const float4* __restrict__ in, float4* __restrict__ outp,
                               const float* __restrict__ scl, const float* __restrict__ sft,
                               int n4) {
    int i = blockIdx.x * blockDim.x + threadIdx.x;
    if (i >= n4) return;
    int c4 = (i & (HWID / 4 - 1)) * 4;
    float4 v = in[i];
    v.x = v.x * scl[c4 + 0] + sft[c4 + 0];
    v.y = v.y * scl[c4 + 1] + sft[c4 + 1];
    v.z = v.z * scl[c4 + 2] + sft[c4 + 2];
    v.w = v.w * scl[c4 + 3] + sft[c4 + 3];
    v.x = v.x > 0.f ? v.x : expm1f(v.x);
    v.y = v.y > 0.f ? v.y : expm1f(v.y);
    v.z = v.z > 0.f ? v.z : expm1f(v.z);
    v.w = v.w > 0.f ? v.w : expm1f(v.w);
    outp[i] = v;
}

// ---------------- host-side orchestration -------------------------------------
#define GEMM3_SMEM 55296

static void run_tf32gemm3(const float* A, const float* B, float* C, int M, int N, int K) {
    dim3 grid(N / 64, (M + 127) / 128);
    tf32gemm3_k<<<grid, 256, GEMM3_SMEM>>>(A, B, C, M, N, K);
}

static void run_sgemm(const float* A, const float* B, float* C, int M, int N, int K,
                      const float* bias, int relu) {
    dim3 grid((N + BN - 1) / BN, (M + BM - 1) / BM);
    sgemm_k<<<grid, 256>>>(A, B, C, M, N, K, bias, relu);
}

static void gat_softmax(const int* src, const int* dst,
                        const float* h, const float* asw, const float* adw,
                        float* asb, float* adb, float* emaxb, float* denb, float* exb,
                        int n, int H)
{
    int nh = n * H;
    attn_coef_k<<<(nh * 32 + 255) / 256, 256>>>(h, asw, adw, asb, adb, n, H);
    fill_k<<<(nh + 255) / 256, 256>>>(emaxb, -3.4e38f, nh);
    fill_k<<<(nh + 255) / 256, 256>>>(denb, 0.f, nh);
    int etH = ET_EDGES * H;
    edge_max_k<<<(etH + 255) / 256, 256>>>(src, dst, asb, adb, emaxb, N_EDGES, ET_EDGES, H);
    edge_exp_k<<<(etH + 255) / 256, 256>>>(src, dst, asb, adb, emaxb, denb, exb, N_EDGES, ET_EDGES, H);
}

static void bn_elu(const float* in, float* outp, const float* g, const float* be, int n,
                   float* sumb, float* sqb, float* sclb, float* sftb)
{
    fill_k<<<1, 256>>>(sumb, 0.f, HWID);
    fill_k<<<1, 256>>>(sqb, 0.f, HWID);
    bn_stats_k<<<512, 256>>>(in, n, sumb, sqb);
    bn_fin_k<<<1, 256>>>(sumb, sqb, g, be, n, sclb, sftb);
    bn_apply_elu_k<<<(n * HWID / 4 + 255) / 256, 256>>>(
        (const float4*)in, (float4*)outp, sclb, sftb, n * HWID / 4);
}

extern "C" void kernel_launch(void* const* d_in, const int* in_sizes, int n_in,
                              void* d_out, int out_size)
{
    const float* x   = (const float*)d_in[0];
    const int*   ei  = (const int*)  d_in[1];
    const float* W0  = (const float*)d_in[2];
    const float* as0 = (const float*)d_in[3];
    const float* ad0 = (const float*)d_in[4];
    // b0 (d_in[5]) cancels through BatchNorm — skipped
    const float* W1  = (const float*)d_in[6];
    const float* as1 = (const float*)d_in[7];
    const float* ad1 = (const float*)d_in[8];
    // b1 (d_in[9]) cancels through BatchNorm — skipped
    const float* W2  = (const float*)d_in[10];
    const float* as2 = (const float*)d_in[11];
    const float* ad2 = (const float*)d_in[12];
    const float* b2  = (const float*)d_in[13];
    const float* g0  = (const float*)d_in[14];
    const float* be0 = (const float*)d_in[15];
    const float* g1  = (const float*)d_in[16];
    const float* be1 = (const float*)d_in[17];
    const float* Wc1 = (const float*)d_in[18];
    const float* bc1 = (const float*)d_in[19];
    const float* Wc2 = (const float*)d_in[20];
    const float* bc2 = (const float*)d_in[21];
    float* out = (float*)d_out;

    const int n = N_NODES;
    const int* src = ei;
    const int* dst = ei + N_EDGES;

    static int smem_cfg_done = 0;
    if (!smem_cfg_done) {
        cudaFuncSetAttribute(tf32gemm3_k,
                             cudaFuncAttributeMaxDynamicSharedMemorySize, GEMM3_SMEM);
        smem_cfg_done = 1;
    }

    float *hbuf, *aggbuf, *asb, *adb, *emaxb, *denb, *exb;
    float *sumb, *sqb, *sclb, *sftb, *clsb;
    int *degb, *curb, *rowb, *eixb, *blkb;
    cudaGetSymbolAddress((void**)&hbuf,  g_h);
    cudaGetSymbolAddress((void**)&aggbuf, g_agg);
    cudaGetSymbolAddress((void**)&asb,   g_as);
    cudaGetSymbolAddress((void**)&adb,   g_ad);
    cudaGetSymbolAddress((void**)&emaxb, g_emax);
    cudaGetSymbolAddress((void**)&denb,  g_den);
    cudaGetSymbolAddress((void**)&exb,   g_ex);
    cudaGetSymbolAddress((void**)&sumb,  g_sum);
    cudaGetSymbolAddress((void**)&sqb,   g_sq);
    cudaGetSymbolAddress((void**)&sclb,  g_scl);
    cudaGetSymbolAddress((void**)&sftb,  g_sft);
    cudaGetSymbolAddress((void**)&clsb,  g_cls);
    cudaGetSymbolAddress((void**)&degb,  g_deg);
    cudaGetSymbolAddress((void**)&curb,  g_cursor);
    cudaGetSymbolAddress((void**)&rowb,  g_rowptr);
    cudaGetSymbolAddress((void**)&eixb,  g_eidx);
    cudaGetSymbolAddress((void**)&blkb,  g_blksum);

    // ---- CSR build (once per call; shared by all three layers) ----
    filli_k<<<(n + 255) / 256, 256>>>(degb, n);
    filli_k<<<(n + 255) / 256, 256>>>(curb, n);
    deg_k<<<(ET_EDGES + 255) / 256, 256>>>(dst, degb, N_EDGES, ET_EDGES);
    scan_part_k<<<NBLK_SCAN, 256>>>(degb, rowb, blkb, n);
    scan_tops_k<<<1, 256>>>(blkb, NBLK_SCAN);
    scan_write_k<<<NBLK_SCAN, 256>>>(rowb, blkb, n);
    fill_pos_k<<<(ET_EDGES + 255) / 256, 256>>>(dst, rowb, curb, eixb, N_EDGES, ET_EDGES);

    int aggBlocks = (n * 32 + 255) / 256;

    // ---- GAT layer 0: 128 -> 4x64 (concat) ----
    run_tf32gemm3(x, W0, hbuf, n, 256, 128);
    gat_softmax(src, dst, hbuf, as0, ad0, asb, adb, emaxb, denb, exb, n, 4);
    agg4_k<<<aggBlocks, 256>>>(rowb, eixb, src, hbuf, exb, denb, aggbuf, n, N_EDGES);
    bn_elu(aggbuf, hbuf, g0, be0, n, sumb, sqb, sclb, sftb);

    // ---- GAT layer 1: 256 -> 4x64 (concat) ----
    run_tf32gemm3(hbuf, W1, aggbuf, n, 256, 256);
    gat_softmax(src, dst, aggbuf, as1, ad1, asb, adb, emaxb, denb, exb, n, 4);
    agg4_k<<<aggBlocks, 256>>>(rowb, eixb, src, aggbuf, exb, denb, hbuf, n, N_EDGES);
    bn_elu(hbuf, aggbuf, g1, be1, n, sumb, sqb, sclb, sftb);

    // ---- GAT layer 2: 256 -> 1x64 (mean over 1 head = identity) + bias ----
    run_tf32gemm3(aggbuf, W2, hbuf, n, 64, 256);
    gat_softmax(src, dst, hbuf, as2, ad2, asb, adb, emaxb, denb, exb, n, 1);
    agg1_k<<<aggBlocks, 256>>>(rowb, eixb, src, hbuf, exb, denb, b2, aggbuf, n, N_EDGES);

    // ---- classifier: 64 -> 32 (relu) -> 2 ----
    run_sgemm(aggbuf, Wc1, clsb, n, 32, 64, bc1, 1);
    run_sgemm(clsb, Wc2, out, n, 2, 32, bc2, 0);
}

// round 5
// speedup vs baseline: 1.7422x; 1.0829x over previous
#include <cuda_runtime.h>
#include <math.h>

// Problem constants (fixed by the dataset)
#define N_NODES 50000
#define N_EDGES 800000
#define ET_EDGES (N_NODES + N_EDGES)   // edges + self loops
#define HWID 256                        // heads*hid for layers 0/1
#define CDIM 64
#define NBLK_SCAN ((N_NODES + 255) / 256)   // 196

// ---------------- scratch (device globals; no allocation allowed) -------------
static __device__ float g_h   [(size_t)N_NODES * HWID];
static __device__ float g_agg [(size_t)N_NODES * HWID];
static __device__ float g_as  [N_NODES * 4];
static __device__ float g_ad  [N_NODES * 4];
static __device__ float g_sum [HWID];
static __device__ float g_sq  [HWID];
static __device__ float g_scl [HWID];
static __device__ float g_sft [HWID];
static __device__ float g_cls [N_NODES * 32];
// CSR scratch
static __device__ int g_deg   [N_NODES];
static __device__ int g_cursor[N_NODES];
static __device__ int g_rowptr[N_NODES + 1];
static __device__ int g_csrc  [ET_EDGES];      // src node per CSR slot
static __device__ int g_blksum[256];

// ---------------- helpers -----------------------------------------------------
__device__ __forceinline__ unsigned int f2tf32(float f) {
    unsigned int u;
    asm("cvt.rna.tf32.f32 %0, %1;" : "=r"(u) : "f"(f));
    return u;
}

__global__ void fill_k(float* p, float v, int n) {
    int i = blockIdx.x * blockDim.x + threadIdx.x;
    if (i < n) p[i] = v;
}

__global__ void filli_k(int* p, int n) {
    int i = blockIdx.x * blockDim.x + threadIdx.x;
    if (i < n) p[i] = 0;
}

// ---------------- CSR construction --------------------------------------------
__global__ void deg_k(const int* __restrict__ dst, int* deg, int E, int et) {
    int e = blockIdx.x * blockDim.x + threadIdx.x;
    if (e >= et) return;
    int d = e < E ? dst[e] : e - E;
    atomicAdd(&deg[d], 1);
}

__global__ void scan_part_k(const int* __restrict__ deg, int* rowptr, int* blksum, int n) {
    __shared__ int sm[256];
    int i = blockIdx.x * 256 + threadIdx.x;
    int v = (i < n) ? deg[i] : 0;
    sm[threadIdx.x] = v;
    __syncthreads();
    for (int o = 1; o < 256; o <<= 1) {
        int t = (threadIdx.x >= o) ? sm[threadIdx.x - o] : 0;
        __syncthreads();
        sm[threadIdx.x] += t;
        __syncthreads();
    }
    if (i < n) rowptr[i] = sm[threadIdx.x] - v;      // exclusive
    if (threadIdx.x == 255) blksum[blockIdx.x] = sm[255];
}

__global__ void scan_tops_k(int* blksum, int nb) {
    __shared__ int sm[256];
    int v = (threadIdx.x < nb) ? blksum[threadIdx.x] : 0;
    sm[threadIdx.x] = v;
    __syncthreads();
    for (int o = 1; o < 256; o <<= 1) {
        int t = (threadIdx.x >= o) ? sm[threadIdx.x - o] : 0;
        __syncthreads();
        sm[threadIdx.x] += t;
        __syncthreads();
    }
    if (threadIdx.x < nb) blksum[threadIdx.x] = sm[threadIdx.x] - v;   // exclusive
}

__global__ void scan_write_k(int* rowptr, const int* __restrict__ blksum, int n) {
    int i = blockIdx.x * 256 + threadIdx.x;
    if (i < n) rowptr[i] += blksum[blockIdx.x];
    if (i == 0) rowptr[n] = ET_EDGES;
}

__global__ void fill_pos_k(const int* __restrict__ src, const int* __restrict__ dst,
                           const int* __restrict__ rowptr,
                           int* cursor, int* csrc, int E, int et) {
    int e = blockIdx.x * blockDim.x + threadIdx.x;
    if (e >= et) return;
    int s, d;
    if (e < E) { s = src[e]; d = dst[e]; } else { s = d = e - E; }
    int p = atomicAdd(&cursor[d], 1);
    csrc[rowptr[d] + p] = s;
}

// ---------------- 3xTF32 tensor-core GEMM: C = A @ B (fp32-accurate) ----------
// BM=128, BN=64, BK=32; 256 threads = 8 warps (4x2), warp tile 32x32.
// Requires: K % 32 == 0, N % 64 == 0. Dynamic smem = 55296 bytes.
__global__ __launch_bounds__(256) void tf32gemm3_k(
    const float* __restrict__ A, const float* __restrict__ B,
    float* __restrict__ C, int M, int N, int K)
{
    extern __shared__ float smem[];
    float (*Ah)[36] = (float(*)[36])(smem);                 // 128*36
    float (*Al)[36] = (float(*)[36])(smem + 4608);          // 128*36
    float (*Bh)[72] = (float(*)[72])(smem + 9216);          // 32*72
    float (*Bl)[72] = (float(*)[72])(smem + 11520);         // 32*72

    int tid = threadIdx.x;
    int warp = tid >> 5, lane = tid & 31;
    int wm = (warp & 3) * 32;
    int wn = (warp >> 2) * 32;
    int rowBase = blockIdx.y * 128;
    int colBase = blockIdx.x * 64;
    int mrow = lane >> 2;           // 0..7
    int kcol = lane & 3;            // 0..3

    float acc[2][4][4];
#pragma unroll
    for (int mi = 0; mi < 2; mi++)
#pragma unroll
        for (int ni = 0; ni < 4; ni++)
#pragma unroll
            for (int r = 0; r < 4; r++) acc[mi][ni][r] = 0.f;

    for (int k0 = 0; k0 < K; k0 += 32) {
#pragma unroll
        for (int i = 0; i < 4; i++) {
            int f4 = tid + i * 256;
            int r = f4 >> 3, c4 = (f4 & 7) * 4;
            int gr = rowBase + r;
            float4 v = make_float4(0.f, 0.f, 0.f, 0.f);
            if (gr < M) v = *(const float4*)&A[(size_t)gr * K + k0 + c4];
            float hx = __uint_as_float(f2tf32(v.x));
            float hy = __uint_as_float(f2tf32(v.y));
            float hz = __uint_as_float(f2tf32(v.z));
            float hw = __uint_as_float(f2tf32(v.w));
            Ah[r][c4 + 0] = hx; Al[r][c4 + 0] = __uint_as_float(f2tf32(v.x - hx));
            Ah[r][c4 + 1] = hy; Al[r][c4 + 1] = __uint_as_float(f2tf32(v.y - hy));
            Ah[r][c4 + 2] = hz; Al[r][c4 + 2] = __uint_as_float(f2tf32(v.z - hz));
            Ah[r][c4 + 3] = hw; Al[r][c4 + 3] = __uint_as_float(f2tf32(v.w - hw));
        }
#pragma unroll
        for (int i = 0; i < 2; i++) {
            int f4 = tid + i * 256;
            int r = f4 >> 4, c4 = (f4 & 15) * 4;
            float4 v = *(const float4*)&B[(size_t)(k0 + r) * N + colBase + c4];
            float hx = __uint_as_float(f2tf32(v.x));
            float hy = __uint_as_float(f2tf32(v.y));
            float hz = __uint_as_float(f2tf32(v.z));
            float hw = __uint_as_float(f2tf32(v.w));
            Bh[r][c4 + 0] = hx; Bl[r][c4 + 0] = __uint_as_float(f2tf32(v.x - hx));
            Bh[r][c4 + 1] = hy; Bl[r][c4 + 1] = __uint_as_float(f2tf32(v.y - hy));
            Bh[r][c4 + 2] = hz; Bl[r][c4 + 2] = __uint_as_float(f2tf32(v.z - hz));
            Bh[r][c4 + 3] = hw; Bl[r][c4 + 3] = __uint_as_float(f2tf32(v.w - hw));
        }
        __syncthreads();

#pragma unroll
        for (int ks = 0; ks < 4; ks++) {
            int kk = ks * 8;
            unsigned int ah[2][4], al[2][4], bh[4][2], bl[4][2];
#pragma unroll
            for (int mi = 0; mi < 2; mi++) {
                int m = wm + mi * 16 + mrow;
                ah[mi][0] = __float_as_uint(Ah[m][kk + kcol]);
                ah[mi][1] = __float_as_uint(Ah[m + 8][kk + kcol]);
                ah[mi][2] = __float_as_uint(Ah[m][kk + kcol + 4]);
                ah[mi][3] = __float_as_uint(Ah[m + 8][kk + kcol + 4]);
                al[mi][0] = __float_as_uint(Al[m][kk + kcol]);
                al[mi][1] = __float_as_uint(Al[m + 8][kk + kcol]);
                al[mi][2] = __float_as_uint(Al[m][kk + kcol + 4]);
                al[mi][3] = __float_as_uint(Al[m + 8][kk + kcol + 4]);
            }
#pragma unroll
            for (int ni = 0; ni < 4; ni++) {
                int nn = wn + ni * 8 + mrow;
                bh[ni][0] = __float_as_uint(Bh[kk + kcol][nn]);
                bh[ni][1] = __float_as_uint(Bh[kk + kcol + 4][nn]);
                bl[ni][0] = __float_as_uint(Bl[kk + kcol][nn]);
                bl[ni][1] = __float_as_uint(Bl[kk + kcol + 4][nn]);
            }
#define MMA_T(ar, br, mi, ni)                                                     \
    asm volatile(                                                                 \
        "mma.sync.aligned.m16n8k8.row.col.f32.tf32.tf32.f32 "                     \
        "{%0,%1,%2,%3},{%4,%5,%6,%7},{%8,%9},{%0,%1,%2,%3};"                      \
        : "+f"(acc[mi][ni][0]), "+f"(acc[mi][ni][1]),                             \
          "+f"(acc[mi][ni][2]), "+f"(acc[mi][ni][3])                              \
        : "r"(ar[mi][0]), "r"(ar[mi][1]), "r"(ar[mi][2]), "r"(ar[mi][3]),         \
          "r"(br[ni][0]), "r"(br[ni][1]))
#pragma unroll
            for (int mi = 0; mi < 2; mi++)
#pragma unroll
                for (int ni = 0; ni < 4; ni++) {
                    MMA_T(ah, bl, mi, ni);
                    MMA_T(al, bh, mi, ni);
                    MMA_T(ah, bh, mi, ni);
                }
#undef MMA_T
        }
        __syncthreads();
    }

#pragma unroll
    for (int mi = 0; mi < 2; mi++) {
        int r0 = rowBase + wm + mi * 16 + mrow;
#pragma unroll
        for (int ni = 0; ni < 4; ni++) {
            int c = colBase + wn + ni * 8 + kcol * 2;
            if (r0 < M) {
                C[(size_t)r0 * N + c]     = acc[mi][ni][0];
                C[(size_t)r0 * N + c + 1] = acc[mi][ni][1];
            }
            if (r0 + 8 < M) {
                C[(size_t)(r0 + 8) * N + c]     = acc[mi][ni][2];
                C[(size_t)(r0 + 8) * N + c + 1] = acc[mi][ni][3];
            }
        }
    }
}

// ---------------- fallback SGEMM (small classifier GEMMs) ---------------------
#define BM 128
#define BN 64
#define BK 16
#define TM 8
#define TN 4
__global__ __launch_bounds__(256) void sgemm_k(
    const float* __restrict__ A, const float* __restrict__ B,
    float* __restrict__ C, int M, int N, int K,
    const float* __restrict__ bias, int relu)
{
    __shared__ float As[BK][BM];
    __shared__ float Bs[BK][BN];
    int tid = threadIdx.x;
    int tx = tid % (BN / TN);
    int ty = tid / (BN / TN);
    int rowBase = blockIdx.y * BM;
    int colBase = blockIdx.x * BN;

    float acc[TM][TN];
#pragma unroll
    for (int i = 0; i < TM; i++)
#pragma unroll
        for (int j = 0; j < TN; j++) acc[i][j] = 0.f;

    for (int k0 = 0; k0 < K; k0 += BK) {
        for (int i = tid; i < BM * BK; i += 256) {
            int r = i / BK, c = i % BK;
            int gr = rowBase + r, gc = k0 + c;
            As[c][r] = (gr < M && gc < K) ? A[(size_t)gr * K + gc] : 0.f;
        }
        for (int i = tid; i < BK * BN; i += 256) {
            int r = i / BN, c = i % BN;
            int gr = k0 + r, gc = colBase + c;
            Bs[r][c] = (gr < K && gc < N) ? B[(size_t)gr * N + gc] : 0.f;
        }
        __syncthreads();
#pragma unroll
        for (int k = 0; k < BK; k++) {
            float a[TM], b[TN];
#pragma unroll
            for (int i = 0; i < TM; i++) a[i] = As[k][ty * TM + i];
#pragma unroll
            for (int j = 0; j < TN; j++) b[j] = Bs[k][tx * TN + j];
#pragma unroll
            for (int i = 0; i < TM; i++)
#pragma unroll
                for (int j = 0; j < TN; j++) acc[i][j] += a[i] * b[j];
        }
        __syncthreads();
    }
#pragma unroll
    for (int i = 0; i < TM; i++) {
        int gr = rowBase + ty * TM + i;
        if (gr >= M) continue;
#pragma unroll
        for (int j = 0; j < TN; j++) {
            int gc = colBase + tx * TN + j;
            if (gc >= N) continue;
            float v = acc[i][j];
            if (bias) v += bias[gc];
            if (relu) v = fmaxf(v, 0.f);
            C[(size_t)gr * N + gc] = v;
        }
    }
}

// ---------------- attention coefficients: a_s[n,h], a_d[n,h] ------------------
__global__ void attn_coef_k(const float* __restrict__ h,
                            const float* __restrict__ asw,
                            const float* __restrict__ adw,
                            float* __restrict__ as_o, float* __restrict__ ad_o,
                            int n, int H)
{
    int w = (blockIdx.x * blockDim.x + threadIdx.x) >> 5;
    int lane = threadIdx.x & 31;
    if (w >= n * H) return;
    int node = w / H, hd = w - node * H;
    const float* row = h + (size_t)node * H * CDIM + hd * CDIM;
    float s = 0.f, d = 0.f;
#pragma unroll
    for (int c = lane; c < CDIM; c += 32) {
        float v = row[c];
        s += v * asw[hd * CDIM + c];
        d += v * adw[hd * CDIM + c];
    }
#pragma unroll
    for (int o = 16; o; o >>= 1) {
        s += __shfl_down_sync(0xFFFFFFFFu, s, o);
        d += __shfl_down_sync(0xFFFFFFFFu, d, o);
    }
    if (!lane) { as_o[w] = s; ad_o[w] = d; }
}

// ---------------- fused softmax + CSR aggregation (H=4) -----------------------
// One warp per dst node. Pass 1: per-head max over neighborhood.
// Pass 2: w = exp(e-max) (one head per lane, shfl-broadcast), acc += w*h[src],
// den += w; normalize at the end. No atomics, no edge-order buffers.
__global__ void agg4_k(const int* __restrict__ rowptr, const int* __restrict__ csrc,
                       const float* __restrict__ h,
                       const float* __restrict__ asb, const float* __restrict__ adb,
                       float* __restrict__ out, int n)
{
    int w = (blockIdx.x * blockDim.x + threadIdx.x) >> 5;
    int lane = threadIdx.x & 31;
    if (w >= n) return;
    int beg = rowptr[w], end = rowptr[w + 1];
    float4 ad4 = *(const float4*)&adb[(size_t)w * 4];

    // pass 1: per-head neighborhood max (all lanes redundant; broadcast loads)
    float4 mx = make_float4(-3.4e38f, -3.4e38f, -3.4e38f, -3.4e38f);
    for (int j = beg; j < end; j++) {
        int s = __ldg(&csrc[j]);
        float4 e4 = *(const float4*)&asb[(size_t)s * 4];
        e4.x += ad4.x; e4.y += ad4.y; e4.z += ad4.z; e4.w += ad4.w;
        e4.x = e4.x > 0.f ? e4.x : 0.2f * e4.x;
        e4.y = e4.y > 0.f ? e4.y : 0.2f * e4.y;
        e4.z = e4.z > 0.f ? e4.z : 0.2f * e4.z;
        e4.w = e4.w > 0.f ? e4.w : 0.2f * e4.w;
        mx.x = fmaxf(mx.x, e4.x); mx.y = fmaxf(mx.y, e4.y);
        mx.z = fmaxf(mx.z, e4.z); mx.w = fmaxf(mx.w, e4.w);
    }

    // lane-distributed exp: lane computes head (lane&3)
    int eh = lane & 3;
    float mx_h = eh == 0 ? mx.x : (eh == 1 ? mx.y : (eh == 2 ? mx.z : mx.w));
    float ad_h = eh == 0 ? ad4.x : (eh == 1 ? ad4.y : (eh == 2 ? ad4.z : ad4.w));
    int hA = lane >> 4;        // head for channels [lane*4 .. ]: 0 or 1
    int hB = 2 + hA;           // head for channels [128 + lane*4 .. ]: 2 or 3

    float4 acc0 = make_float4(0.f, 0.f, 0.f, 0.f);
    float4 acc1 = make_float4(0.f, 0.f, 0.f, 0.f);
    float den = 0.f;
    for (int j = beg; j < end; j++) {
        int s = __ldg(&csrc[j]);
        float e = asb[(size_t)s * 4 + eh] + ad_h;
        e = e > 0.f ? e : 0.2f * e;
        float ww = __expf(e - mx_h);
        den += ww;
        float aA = __shfl_sync(0xFFFFFFFFu, ww, hA);
        float aB = __shfl_sync(0xFFFFFFFFu, ww, hB);
        const float4* hr = (const float4*)(h + (size_t)s * 256);
        float4 v0 = hr[lane];
        float4 v1 = hr[32 + lane];
        acc0.x += v0.x * aA; acc0.y += v0.y * aA; acc0.z += v0.z * aA; acc0.w += v0.w * aA;
        acc1.x += v1.x * aB; acc1.y += v1.y * aB; acc1.z += v1.z * aB; acc1.w += v1.w * aB;
    }
    float iA = 1.f / __shfl_sync(0xFFFFFFFFu, den, hA);
    float iB = 1.f / __shfl_sync(0xFFFFFFFFu, den, hB);
    acc0.x *= iA; acc0.y *= iA; acc0.z *= iA; acc0.w *= iA;
    acc1.x *= iB; acc1.y *= iB; acc1.z *= iB; acc1.w *= iB;
    float4* o4 = (float4*)(out + (size_t)w * 256);
    o4[lane] = acc0;
    o4[32 + lane] = acc1;
}

// ---------------- fused softmax + CSR aggregation (H=1) + bias ----------------
__global__ void agg1_k(const int* __restrict__ rowptr, const int* __restrict__ csrc,
                       const float* __restrict__ h,
                       const float* __restrict__ asb, const float* __restrict__ adb,
                       const float* __restrict__ bias,
                       float* __restrict__ out, int n)
{
    int w = (blockIdx.x * blockDim.x + threadIdx.x) >> 5;
    int lane = threadIdx.x & 31;
    if (w >= n) return;
    int beg = rowptr[w], end = rowptr[w + 1];
    float ad = adb[w];

    float mx = -3.4e38f;
    for (int j = beg; j < end; j++) {
        int s = __ldg(&csrc[j]);
        float e = asb[s] + ad;
        e = e > 0.f ? e : 0.2f * e;
        mx = fmaxf(mx, e);
    }

    float den = 0.f;
    float4 acc = make_float4(0.f, 0.f, 0.f, 0.f);
    for (int j = beg; j < end; j++) {
        int s = __ldg(&csrc[j]);
        float e = asb[s] + ad;
        e = e > 0.f ? e : 0.2f * e;
        float ww = __expf(e - mx);
        den += ww;
        if (lane < 16) {
            float4 v = ((const float4*)(h + (size_t)s * 64))[lane];
            acc.x += v.x * ww; acc.y += v.y * ww; acc.z += v.z * ww; acc.w += v.w * ww;
        }
    }
    if (lane < 16) {
        float inv = 1.f / den;
        float4 b4 = ((const float4*)bias)[lane];
        acc.x = acc.x * inv + b4.x; acc.y = acc.y * inv + b4.y;
        acc.z = acc.z * inv + b4.z; acc.w = acc.w * inv + b4.w;
        ((float4*)(out + (size_t)w * 64))[lane] = acc;
    }
}

// ---------------- batch norm (C=256 channels) ---------------------------------
__global__ void bn_stats_k(const float* __restrict__ x, int n, float* sum, float* sq) {
    int ch = threadIdx.x;
    float s = 0.f, s2 = 0.f;
    for (int r = blockIdx.x; r < n; r += gridDim.x) {
        float v = x[(size_t)r * HWID + ch];
        s += v; s2 += v * v;
    }
    atomicAdd(&sum[ch], s);
    atomicAdd(&sq[ch], s2);
}

__global__ void bn_fin_k(const float* sum, const float* sq,
                         const float* __restrict__ g, const float* __restrict__ be,
                         int n, float* scl, float* sft) {
    int ch = threadIdx.x;
    float mu = sum[ch] / (float)n;
    float var = fmaxf(sq[ch] / (float)n - mu * mu, 0.f);
    float r = rsqrtf(var + 1e-5f);
    float s = g[ch] * r;
    scl[ch] = s;
    sft[ch] = be[ch] - mu * s;
}

__global__ void bn_apply_elu_k(const float4* __restrict__ in, float4* __restrict__ outp,
                               const float* __restrict__ scl, const float* __restrict__ sft,
                               int n4) {
    int i = blockIdx.x * blockDim.x + threadIdx.x;
    if (i >= n4) return;
    int c4 = (i & (HWID / 4 - 1)) * 4;
    float4 v = in[i];
    v.x = v.x * scl[c4 + 0] + sft[c4 + 0];
    v.y = v.y * scl[c4 + 1] + sft[c4 + 1];
    v.z = v.z * scl[c4 + 2] + sft[c4 + 2];
    v.w = v.w * scl[c4 + 3] + sft[c4 + 3];
    v.x = v.x > 0.f ? v.x : expm1f(v.x);
    v.y = v.y > 0.f ? v.y : expm1f(v.y);
    v.z = v.z > 0.f ? v.z : expm1f(v.z);
    v.w = v.w > 0.f ? v.w : expm1f(v.w);
    outp[i] = v;
}

// ---------------- host-side orchestration -------------------------------------
#define GEMM3_SMEM 55296

static void run_tf32gemm3(const float* A, const float* B, float* C, int M, int N, int K) {
    dim3 grid(N / 64, (M + 127) / 128);
    tf32gemm3_k<<<grid, 256, GEMM3_SMEM>>>(A, B, C, M, N, K);
}

static void run_sgemm(const float* A, const float* B, float* C, int M, int N, int K,
                      const float* bias, int relu) {
    dim3 grid((N + BN - 1) / BN, (M + BM - 1) / BM);
    sgemm_k<<<grid, 256>>>(A, B, C, M, N, K, bias, relu);
}

static void bn_elu(const float* in, float* outp, const float* g, const float* be, int n,
                   float* sumb, float* sqb, float* sclb, float* sftb)
{
    fill_k<<<1, 256>>>(sumb, 0.f, HWID);
    fill_k<<<1, 256>>>(sqb, 0.f, HWID);
    bn_stats_k<<<512, 256>>>(in, n, sumb, sqb);
    bn_fin_k<<<1, 256>>>(sumb, sqb, g, be, n, sclb, sftb);
    bn_apply_elu_k<<<(n * HWID / 4 + 255) / 256, 256>>>(
        (const float4*)in, (float4*)outp, sclb, sftb, n * HWID / 4);
}

extern "C" void kernel_launch(void* const* d_in, const int* in_sizes, int n_in,
                              void* d_out, int out_size)
{
    const float* x   = (const float*)d_in[0];
    const int*   ei  = (const int*)  d_in[1];
    const float* W0  = (const float*)d_in[2];
    const float* as0 = (const float*)d_in[3];
    const float* ad0 = (const float*)d_in[4];
    // b0 (d_in[5]) cancels through BatchNorm — skipped
    const float* W1  = (const float*)d_in[6];
    const float* as1 = (const float*)d_in[7];
    const float* ad1 = (const float*)d_in[8];
    // b1 (d_in[9]) cancels through BatchNorm — skipped
    const float* W2  = (const float*)d_in[10];
    const float* as2 = (const float*)d_in[11];
    const float* ad2 = (const float*)d_in[12];
    const float* b2  = (const float*)d_in[13];
    const float* g0  = (const float*)d_in[14];
    const float* be0 = (const float*)d_in[15];
    const float* g1  = (const float*)d_in[16];
    const float* be1 = (const float*)d_in[17];
    const float* Wc1 = (const float*)d_in[18];
    const float* bc1 = (const float*)d_in[19];
    const float* Wc2 = (const float*)d_in[20];
    const float* bc2 = (const float*)d_in[21];
    float* out = (float*)d_out;

    const int n = N_NODES;
    const int* src = ei;
    const int* dst = ei + N_EDGES;

    static int smem_cfg_done = 0;
    if (!smem_cfg_done) {
        cudaFuncSetAttribute(tf32gemm3_k,
                             cudaFuncAttributeMaxDynamicSharedMemorySize, GEMM3_SMEM);
        smem_cfg_done = 1;
    }

    float *hbuf, *aggbuf, *asb, *adb;
    float *sumb, *sqb, *sclb, *sftb, *clsb;
    int *degb, *curb, *rowb, *csrcb, *blkb;
    cudaGetSymbolAddress((void**)&hbuf,  g_h);
    cudaGetSymbolAddress((void**)&aggbuf, g_agg);
    cudaGetSymbolAddress((void**)&asb,   g_as);
    cudaGetSymbolAddress((void**)&adb,   g_ad);
    cudaGetSymbolAddress((void**)&sumb,  g_sum);
    cudaGetSymbolAddress((void**)&sqb,   g_sq);
    cudaGetSymbolAddress((void**)&sclb,  g_scl);
    cudaGetSymbolAddress((void**)&sftb,  g_sft);
    cudaGetSymbolAddress((void**)&clsb,  g_cls);
    cudaGetSymbolAddress((void**)&degb,  g_deg);
    cudaGetSymbolAddress((void**)&curb,  g_cursor);
    cudaGetSymbolAddress((void**)&rowb,  g_rowptr);
    cudaGetSymbolAddress((void**)&csrcb, g_csrc);
    cudaGetSymbolAddress((void**)&blkb,  g_blksum);

    // ---- CSR build (once per call; shared by all three layers) ----
    filli_k<<<(n + 255) / 256, 256>>>(degb, n);
    filli_k<<<(n + 255) / 256, 256>>>(curb, n);
    deg_k<<<(ET_EDGES + 255) / 256, 256>>>(dst, degb, N_EDGES, ET_EDGES);
    scan_part_k<<<NBLK_SCAN, 256>>>(degb, rowb, blkb, n);
    scan_tops_k<<<1, 256>>>(blkb, NBLK_SCAN);
    scan_write_k<<<NBLK_SCAN, 256>>>(rowb, blkb, n);
    fill_pos_k<<<(ET_EDGES + 255) / 256, 256>>>(src, dst, rowb, curb, csrcb,
                                                N_EDGES, ET_EDGES);

    int aggBlocks = (n * 32 + 255) / 256;

    // ---- GAT layer 0: 128 -> 4x64 (concat) ----
    run_tf32gemm3(x, W0, hbuf, n, 256, 128);
    attn_coef_k<<<(n * 4 * 32 + 255) / 256, 256>>>(hbuf, as0, ad0, asb, adb, n, 4);
    agg4_k<<<aggBlocks, 256>>>(rowb, csrcb, hbuf, asb, adb, aggbuf, n);
    bn_elu(aggbuf, hbuf, g0, be0, n, sumb, sqb, sclb, sftb);

    // ---- GAT layer 1: 256 -> 4x64 (concat) ----
    run_tf32gemm3(hbuf, W1, aggbuf, n, 256, 256);
    attn_coef_k<<<(n * 4 * 32 + 255) / 256, 256>>>(aggbuf, as1, ad1, asb, adb, n, 4);
    agg4_k<<<aggBlocks, 256>>>(rowb, csrcb, aggbuf, asb, adb, hbuf, n);
    bn_elu(hbuf, aggbuf, g1, be1, n, sumb, sqb, sclb, sftb);

    // ---- GAT layer 2: 256 -> 1x64 (mean over 1 head = identity) + bias ----
    run_tf32gemm3(aggbuf, W2, hbuf, n, 64, 256);
    attn_coef_k<<<(n * 32 + 255) / 256, 256>>>(hbuf, as2, ad2, asb, adb, n, 1);
    agg1_k<<<aggBlocks, 256>>>(rowb, csrcb, hbuf, asb, adb, b2, aggbuf, n);

    // ---- classifier: 64 -> 32 (relu) -> 2 ----
    run_sgemm(aggbuf, Wc1, clsb, n, 32, 64, bc1, 1);
    run_sgemm(clsb, Wc2, out, n, 2, 32, bc2, 0);
}